// round 4
// baseline (speedup 1.0000x reference)
#include <cuda_runtime.h>

#define NN 128
#define TT 2048
#define DD 88
#define D4 22                 // float4 per row
#define ROWS 4                // rows per warp
#define K1_THREADS 256
#define K1_WARPS   8
#define K1_BLOCKS  (NN * TT / (ROWS * K1_WARPS))   // 8192

__device__ unsigned int g_stat[NN];          // tp (18 bits) | Ti<<18 ; zero-init, reset by k2
__device__ uint2        g_fpfn2[NN * TT / 8]; // per-row fp+fn counts, 1 byte each
__device__ float        g_acc[NN];
__device__ unsigned int g_count = 0;

// ---------------------------------------------------------------------------
// k1: one warp per 4 consecutive rows. 8 front-batched LDG.128, byte-packed
// warp reduce for fpfn, packed integer warp reduce for tp + mask count.
// ---------------------------------------------------------------------------
__global__ void __launch_bounds__(K1_THREADS) k1_rowstats(
    const float4* __restrict__ outp,
    const float4* __restrict__ tgtp,
    const int*    __restrict__ mask)
{
    const int w    = blockIdx.x * K1_WARPS + (threadIdx.x >> 5);
    const int lane = threadIdx.x & 31;
    const int r0   = w * ROWS;              // global row index (= n*TT + t0)
    const int n    = r0 >> 11;

    const size_t base = (size_t)r0 * D4 + lane;
    const bool   act  = (lane < D4);

    float4 o0, o1, o2, o3, g0, g1, g2, g3;
    if (act) {
        o0 = outp[base];            g0 = tgtp[base];
        o1 = outp[base +     D4];   g1 = tgtp[base +     D4];
        o2 = outp[base + 2 * D4];   g2 = tgtp[base + 2 * D4];
        o3 = outp[base + 3 * D4];   g3 = tgtp[base + 3 * D4];
    }

    int fp = 0;     // 4 rows' fp+fn counts, byte-packed
    int tp = 0;     // true positives (all 4 rows)
    if (act) {
        int f0 = 0, f1 = 0, f2 = 0, f3 = 0;
        #define ELEM(ov, gv, fv) {                       \
            const bool p = ((ov) > 0.f);                 \
            const bool q = ((gv) != 0.f);                \
            tp += (p && q) ? 1 : 0;                      \
            fv += (p != q) ? 1 : 0; }
        ELEM(o0.x, g0.x, f0) ELEM(o0.y, g0.y, f0) ELEM(o0.z, g0.z, f0) ELEM(o0.w, g0.w, f0)
        ELEM(o1.x, g1.x, f1) ELEM(o1.y, g1.y, f1) ELEM(o1.z, g1.z, f1) ELEM(o1.w, g1.w, f1)
        ELEM(o2.x, g2.x, f2) ELEM(o2.y, g2.y, f2) ELEM(o2.z, g2.z, f2) ELEM(o2.w, g2.w, f2)
        ELEM(o3.x, g3.x, f3) ELEM(o3.y, g3.y, f3) ELEM(o3.z, g3.z, f3) ELEM(o3.w, g3.w, f3)
        #undef ELEM
        fp = f0 | (f1 << 8) | (f2 << 16) | (f3 << 24);
    }

    // mask count: lanes 0..3 read mask for the 4 rows
    int ti = (lane < ROWS) ? mask[(size_t)r0 + lane] : 0;
    int v2 = tp | (ti << 16);    // tp <= 512 per warp after reduce, fits 16 bits

    #pragma unroll
    for (int off = 16; off; off >>= 1) {
        fp += __shfl_down_sync(0xffffffffu, fp, off);
        v2 += __shfl_down_sync(0xffffffffu, v2, off);
    }

    if (lane == 0) {
        ((unsigned int*)g_fpfn2)[w] = (unsigned int)fp;   // bytes = rows r0..r0+3
        const unsigned int tpw = (unsigned int)(v2 & 0xffff);
        const unsigned int tiw = (unsigned int)(v2 >> 16);
        atomicAdd(&g_stat[n], tpw + (tiw << 18));
    }
}

// ---------------------------------------------------------------------------
// k2: one block per sequence. Reads fpfn bytes + stat, sums ratios for valid
// timesteps, then deterministic last-block final reduction into out[0].
// ---------------------------------------------------------------------------
__global__ void __launch_bounds__(256) k2_finish(float* __restrict__ out)
{
    const int n    = blockIdx.x;
    const int tid  = threadIdx.x;
    const int warp = tid >> 5;
    const int lane = tid & 31;
    __shared__ float s_redf[8];
    __shared__ int   s_isLast;

    const unsigned int stat = g_stat[n];
    const float tp = (float)(stat & 0x3ffffu);
    const int   Ti = (int)(stat >> 18);

    // 8 rows' fpfn bytes per thread
    const uint2 v = g_fpfn2[n * (TT / 8) + tid];
    const int tbase = tid * 8;

    float acc = 0.f;
    #pragma unroll
    for (int b = 0; b < 8; b++) {
        const unsigned int word = (b < 4) ? v.x : v.y;
        const float f = (float)((word >> ((b & 3) * 8)) & 0xffu);
        if (tbase + b < Ti) acc += __fdividef(tp, tp + f);
    }

    #pragma unroll
    for (int off = 16; off; off >>= 1)
        acc += __shfl_down_sync(0xffffffffu, acc, off);
    if (lane == 0) s_redf[warp] = acc;
    __syncthreads();

    if (tid == 0) {
        float v8 = s_redf[0] + s_redf[1] + s_redf[2] + s_redf[3]
                 + s_redf[4] + s_redf[5] + s_redf[6] + s_redf[7];
        g_acc[n] = v8 / (float)Ti;
        g_stat[n] = 0;                      // reset for next graph replay
        __threadfence();
        unsigned int old = atomicAdd(&g_count, 1u);
        s_isLast = (old == (unsigned)(gridDim.x - 1)) ? 1 : 0;
    }
    __syncthreads();

    if (s_isLast && warp == 0) {
        __threadfence();
        float v = g_acc[lane] + g_acc[lane + 32] + g_acc[lane + 64] + g_acc[lane + 96];
        #pragma unroll
        for (int off = 16; off; off >>= 1)
            v += __shfl_down_sync(0xffffffffu, v, off);
        if (lane == 0) {
            out[0]  = v;
            g_count = 0;
        }
    }
}

extern "C" void kernel_launch(void* const* d_in, const int* in_sizes, int n_in,
                              void* d_out, int out_size)
{
    const float4* outp = (const float4*)d_in[0];
    const float4* tgtp = (const float4*)d_in[1];
    const int*    mask = (const int*)  d_in[2];
    float*        out  = (float*)d_out;

    k1_rowstats<<<K1_BLOCKS, K1_THREADS>>>(outp, tgtp, mask);
    k2_finish<<<NN, 256>>>(out);
}

// round 5
// speedup vs baseline: 1.4188x; 1.4188x over previous
#include <cuda_runtime.h>

#define NN 128
#define TT 2048
#define DD 88
#define D4 22                 // float4 per row
#define ROWS 4                // rows per warp
#define K1_THREADS 256
#define K1_WARPS   8
#define K1_BLOCKS  (NN * TT / (ROWS * K1_WARPS))   // 8192, 64 blocks per n

__device__ unsigned int g_bstat[K1_BLOCKS];   // per-block: tp | (Ti << 16)
__device__ uint2        g_fpfn2[NN * TT / 8]; // per-row fp+fn counts, 1 byte each
__device__ float        g_acc[NN];
__device__ unsigned int g_count = 0;

// ---------------------------------------------------------------------------
// k1: one warp per 4 consecutive rows, 8 front-batched LDG.128.
// Byte-packed warp reduce for fpfn; packed tp|ti warp reduce + smem block
// reduce -> one plain store per block (NO atomics).
// ---------------------------------------------------------------------------
__global__ void __launch_bounds__(K1_THREADS) k1_rowstats(
    const float4* __restrict__ outp,
    const float4* __restrict__ tgtp,
    const int*    __restrict__ mask)
{
    const int warp = threadIdx.x >> 5;
    const int lane = threadIdx.x & 31;
    const int w    = blockIdx.x * K1_WARPS + warp;
    const int r0   = w * ROWS;              // global row index (= n*TT + t0)

    const size_t base = (size_t)r0 * D4 + lane;
    const bool   act  = (lane < D4);

    float4 o0, o1, o2, o3, g0, g1, g2, g3;
    if (act) {
        o0 = outp[base];            g0 = tgtp[base];
        o1 = outp[base +     D4];   g1 = tgtp[base +     D4];
        o2 = outp[base + 2 * D4];   g2 = tgtp[base + 2 * D4];
        o3 = outp[base + 3 * D4];   g3 = tgtp[base + 3 * D4];
    }
    // mask loads on otherwise-idle lanes 22..25
    int ti = (lane >= D4 && lane < D4 + ROWS) ? mask[(size_t)r0 + (lane - D4)] : 0;

    int fp = 0;     // 4 rows' fp+fn counts, byte-packed
    int tp = 0;     // true positives across the 4 rows
    if (act) {
        int f0 = 0, f1 = 0, f2 = 0, f3 = 0;
        #define ELEM(ov, gv, fv) {                       \
            const bool p = ((ov) > 0.f);                 \
            const bool q = ((gv) != 0.f);                \
            tp += (p && q) ? 1 : 0;                      \
            fv += (p != q) ? 1 : 0; }
        ELEM(o0.x, g0.x, f0) ELEM(o0.y, g0.y, f0) ELEM(o0.z, g0.z, f0) ELEM(o0.w, g0.w, f0)
        ELEM(o1.x, g1.x, f1) ELEM(o1.y, g1.y, f1) ELEM(o1.z, g1.z, f1) ELEM(o1.w, g1.w, f1)
        ELEM(o2.x, g2.x, f2) ELEM(o2.y, g2.y, f2) ELEM(o2.z, g2.z, f2) ELEM(o2.w, g2.w, f2)
        ELEM(o3.x, g3.x, f3) ELEM(o3.y, g3.y, f3) ELEM(o3.z, g3.z, f3) ELEM(o3.w, g3.w, f3)
        #undef ELEM
        fp = f0 | (f1 << 8) | (f2 << 16) | (f3 << 24);
    }

    int v2 = tp | (ti << 16);   // warp totals: tp<=352 (16b ok), ti<=4

    #pragma unroll
    for (int off = 16; off; off >>= 1) {
        fp += __shfl_down_sync(0xffffffffu, fp, off);
        v2 += __shfl_down_sync(0xffffffffu, v2, off);
    }

    __shared__ int s_v[K1_WARPS];
    if (lane == 0) {
        ((unsigned int*)g_fpfn2)[w] = (unsigned int)fp;   // bytes = rows r0..r0+3
        s_v[warp] = v2;
    }
    __syncthreads();
    if (threadIdx.x == 0) {
        // block totals: tp<=2816 (16b ok), ti<=32
        int s = s_v[0] + s_v[1] + s_v[2] + s_v[3] + s_v[4] + s_v[5] + s_v[6] + s_v[7];
        g_bstat[blockIdx.x] = (unsigned int)s;
    }
}

// ---------------------------------------------------------------------------
// k2: one block per sequence. fpfn load issued FIRST (independent), bstat
// reduce overlaps it. Then ratio sum + deterministic final reduction.
// ---------------------------------------------------------------------------
__global__ void __launch_bounds__(256) k2_finish(float* __restrict__ out)
{
    const int n    = blockIdx.x;
    const int tid  = threadIdx.x;
    const int warp = tid >> 5;
    const int lane = tid & 31;
    __shared__ int   s_ri[8];
    __shared__ float s_rf[8];
    __shared__ int   s_isLast;

    // issue fpfn load immediately (8 rows' bytes per thread)
    const uint2 v = g_fpfn2[n * (TT / 8) + tid];

    // reduce the 64 per-block stats for this n (overlaps the load above)
    unsigned int bw = (tid < 64) ? g_bstat[n * 64 + tid] : 0u;
    int tpi = (int)(bw & 0xffffu);
    int tii = (int)(bw >> 16);
    int pk  = tpi | (tii << 18);            // tp<=180224 fits 18 bits
    #pragma unroll
    for (int off = 16; off; off >>= 1)
        pk += __shfl_down_sync(0xffffffffu, pk, off);
    if (lane == 0) s_ri[warp] = pk;
    __syncthreads();
    const int tot = s_ri[0] + s_ri[1];      // only warps 0,1 hold bstat data
    const float tp = (float)(tot & 0x3ffff);
    const int   Ti = tot >> 18;

    const int tbase = tid * 8;
    float acc = 0.f;
    #pragma unroll
    for (int b = 0; b < 8; b++) {
        const unsigned int word = (b < 4) ? v.x : v.y;
        const float f = (float)((word >> ((b & 3) * 8)) & 0xffu);
        if (tbase + b < Ti) acc += __fdividef(tp, tp + f);
    }

    #pragma unroll
    for (int off = 16; off; off >>= 1)
        acc += __shfl_down_sync(0xffffffffu, acc, off);
    if (lane == 0) s_rf[warp] = acc;
    __syncthreads();

    if (tid == 0) {
        float v8 = s_rf[0] + s_rf[1] + s_rf[2] + s_rf[3]
                 + s_rf[4] + s_rf[5] + s_rf[6] + s_rf[7];
        g_acc[n] = v8 / (float)Ti;
        __threadfence();
        unsigned int old = atomicAdd(&g_count, 1u);
        s_isLast = (old == (unsigned)(gridDim.x - 1)) ? 1 : 0;
    }
    __syncthreads();

    if (s_isLast && warp == 0) {
        __threadfence();
        float vv = g_acc[lane] + g_acc[lane + 32] + g_acc[lane + 64] + g_acc[lane + 96];
        #pragma unroll
        for (int off = 16; off; off >>= 1)
            vv += __shfl_down_sync(0xffffffffu, vv, off);
        if (lane == 0) {
            out[0]  = vv;
            g_count = 0;    // reset for next graph replay
        }
    }
}

extern "C" void kernel_launch(void* const* d_in, const int* in_sizes, int n_in,
                              void* d_out, int out_size)
{
    const float4* outp = (const float4*)d_in[0];
    const float4* tgtp = (const float4*)d_in[1];
    const int*    mask = (const int*)  d_in[2];
    float*        out  = (float*)d_out;

    k1_rowstats<<<K1_BLOCKS, K1_THREADS>>>(outp, tgtp, mask);
    k2_finish<<<NN, 256>>>(out);
}

// round 7
// speedup vs baseline: 1.5874x; 1.1189x over previous
#include <cuda_runtime.h>

#define NN 128
#define TT 2048
#define DD 88
#define D4 22                    // float4 per row
#define THREADS 256
#define WARPS 8
#define BLK_PER_N 16
#define ROWS_PER_BLK 128         // TT / BLK_PER_N
#define ROWS_PER_WARP 16         // ROWS_PER_BLK / WARPS
#define ITERS 4                  // ROWS_PER_WARP / 4
#define GRID (NN * BLK_PER_N)    // 2048

__device__ float        g_fpfnF[NN * TT];     // per-row fp+fn, as float
__device__ unsigned int g_pstat[GRID];        // per-block tp | ti<<18
__device__ unsigned int g_cnt[NN];            // per-n arrival counter
__device__ float        g_acc[NN];
__device__ unsigned int g_done = 0;

__global__ void __launch_bounds__(THREADS) fused_accuracy(
    const float4* __restrict__ outp,
    const float4* __restrict__ tgtp,
    const int*    __restrict__ mask,
    float*        __restrict__ out)
{
    const int tid  = threadIdx.x;
    const int warp = tid >> 5;
    const int lane = tid & 31;
    const int n    = blockIdx.x >> 4;
    const int sub  = blockIdx.x & 15;
    const int r_w  = n * TT + sub * ROWS_PER_BLK + warp * ROWS_PER_WARP;

    const bool act = (lane < D4);
    int tp = 0;                              // deferred across iters
    int ti = 0;                              // lanes 22..25 accumulate mask

    #pragma unroll
    for (int it = 0; it < ITERS; it++) {
        const int r0 = r_w + it * 4;
        const size_t base = (size_t)r0 * D4 + lane;

        float4 o0, o1, o2, o3, g0, g1, g2, g3;
        if (act) {
            o0 = __ldcs(outp + base);           g0 = __ldcs(tgtp + base);
            o1 = __ldcs(outp + base +     D4);  g1 = __ldcs(tgtp + base +     D4);
            o2 = __ldcs(outp + base + 2 * D4);  g2 = __ldcs(tgtp + base + 2 * D4);
            o3 = __ldcs(outp + base + 3 * D4);  g3 = __ldcs(tgtp + base + 3 * D4);
        }
        if (lane >= D4 && lane < D4 + 4) ti += mask[(size_t)r0 + (lane - D4)];

        int fp = 0;                          // 4 rows byte-packed
        if (act) {
            int f0 = 0, f1 = 0, f2 = 0, f3 = 0;
            #define ELEM(ov, gv, fv) {                    \
                const bool p = ((ov) > 0.f);              \
                const bool q = ((gv) != 0.f);             \
                tp += (p && q) ? 1 : 0;                   \
                fv += (p != q) ? 1 : 0; }
            ELEM(o0.x, g0.x, f0) ELEM(o0.y, g0.y, f0) ELEM(o0.z, g0.z, f0) ELEM(o0.w, g0.w, f0)
            ELEM(o1.x, g1.x, f1) ELEM(o1.y, g1.y, f1) ELEM(o1.z, g1.z, f1) ELEM(o1.w, g1.w, f1)
            ELEM(o2.x, g2.x, f2) ELEM(o2.y, g2.y, f2) ELEM(o2.z, g2.z, f2) ELEM(o2.w, g2.w, f2)
            ELEM(o3.x, g3.x, f3) ELEM(o3.y, g3.y, f3) ELEM(o3.z, g3.z, f3) ELEM(o3.w, g3.w, f3)
            #undef ELEM
            fp = f0 | (f1 << 8) | (f2 << 16) | (f3 << 24);
        }
        #pragma unroll
        for (int off = 16; off; off >>= 1)
            fp += __shfl_down_sync(0xffffffffu, fp, off);

        if (lane == 0) {
            float4 s;
            s.x = (float)( fp        & 0xff);
            s.y = (float)((fp >> 8)  & 0xff);
            s.z = (float)((fp >> 16) & 0xff);
            s.w = (float)((fp >> 24) & 0xff);
            *(float4*)&g_fpfnF[r0] = s;
        }
    }

    // ---- block stat: pack tp | ti<<16 per warp, block reduce, one store ----
    int v2 = tp | (ti << 16);
    #pragma unroll
    for (int off = 16; off; off >>= 1)
        v2 += __shfl_down_sync(0xffffffffu, v2, off);

    __shared__ int   s_v[WARPS];
    __shared__ int   s_role;                 // 0=none, 1=finisher
    __shared__ float s_rf[WARPS];
    __shared__ unsigned int s_stat;
    if (lane == 0) s_v[warp] = v2;
    __syncthreads();
    if (tid == 0) {
        int s = s_v[0] + s_v[1] + s_v[2] + s_v[3] + s_v[4] + s_v[5] + s_v[6] + s_v[7];
        unsigned int tpb = (unsigned int)(s & 0xffff);
        unsigned int tib = (unsigned int)(s >> 16) & 0xffffu;
        g_pstat[blockIdx.x] = tpb | (tib << 18);
    }

    // ---- release + per-n arrival ----
    __threadfence();
    __syncthreads();
    if (tid == 0) {
        unsigned int old = atomicAdd(&g_cnt[n], 1u);
        s_role = (old == BLK_PER_N - 1) ? 1 : 0;
        if (s_role) g_cnt[n] = 0;            // reset for next replay
    }
    __syncthreads();
    if (!s_role) return;

    // ================= finisher for sequence n =================
    __threadfence();                          // acquire

    if (tid < BLK_PER_N) {
        unsigned int v = g_pstat[n * BLK_PER_N + tid];
        #pragma unroll
        for (int off = 8; off; off >>= 1)
            v += __shfl_down_sync(0xffffu, v, off);
        if (tid == 0) s_stat = v;
    }
    __syncthreads();
    const float tpf = (float)(s_stat & 0x3ffffu);
    const int   Ti  = (int)(s_stat >> 18);

    const float4 a = *(const float4*)&g_fpfnF[n * TT + tid * 8];
    const float4 b = *(const float4*)&g_fpfnF[n * TT + tid * 8 + 4];
    const int tb = tid * 8;
    float acc = 0.f;
    if (tb + 0 < Ti) acc += __fdividef(tpf, tpf + a.x);
    if (tb + 1 < Ti) acc += __fdividef(tpf, tpf + a.y);
    if (tb + 2 < Ti) acc += __fdividef(tpf, tpf + a.z);
    if (tb + 3 < Ti) acc += __fdividef(tpf, tpf + a.w);
    if (tb + 4 < Ti) acc += __fdividef(tpf, tpf + b.x);
    if (tb + 5 < Ti) acc += __fdividef(tpf, tpf + b.y);
    if (tb + 6 < Ti) acc += __fdividef(tpf, tpf + b.z);
    if (tb + 7 < Ti) acc += __fdividef(tpf, tpf + b.w);

    #pragma unroll
    for (int off = 16; off; off >>= 1)
        acc += __shfl_down_sync(0xffffffffu, acc, off);
    if (lane == 0) s_rf[warp] = acc;
    __syncthreads();

    if (tid == 0) {
        float v8 = s_rf[0] + s_rf[1] + s_rf[2] + s_rf[3]
                 + s_rf[4] + s_rf[5] + s_rf[6] + s_rf[7];
        g_acc[n] = v8 / (float)Ti;
        __threadfence();
        unsigned int old = atomicAdd(&g_done, 1u);
        s_role = (old == NN - 1) ? 2 : 1;
    }
    __syncthreads();
    if (s_role != 2) return;

    // ================= global finisher =================
    if (warp == 0) {
        __threadfence();
        float v = g_acc[lane] + g_acc[lane + 32] + g_acc[lane + 64] + g_acc[lane + 96];
        #pragma unroll
        for (int off = 16; off; off >>= 1)
            v += __shfl_down_sync(0xffffffffu, v, off);
        if (lane == 0) {
            out[0] = v;
            g_done = 0;                       // reset for next replay
        }
    }
}

extern "C" void kernel_launch(void* const* d_in, const int* in_sizes, int n_in,
                              void* d_out, int out_size)
{
    const float4* outp = (const float4*)d_in[0];
    const float4* tgtp = (const float4*)d_in[1];
    const int*    mask = (const int*)  d_in[2];
    float*        out  = (float*)d_out;

    fused_accuracy<<<GRID, THREADS>>>(outp, tgtp, mask, out);
}